// round 4
// baseline (speedup 1.0000x reference)
#include <cuda_runtime.h>
#include <math.h>

#define NN 50000
#define EE 400000
#define FF 128
#define TF 384

// ---------------- device scratch (static, no allocation) ----------------
__device__ float g_S[NN * FF];        // embedded scalar features s0
__device__ float g_phi[NN * TF];      // phi = MLP(s0)
__device__ float g_h[NN * 256];       // [ :128]=s_msg, [128:256]=Vn
__device__ float g_v[NN * TF];        // message-phase v, layout [n][c][f]
__device__ float g_U[NN * TF];        // U, layout [n][c][f]
__device__ float g_V[NN * TF];        // V, layout [n][c][f]
__device__ float g_a[NN * TF];        // update-MLP output a
__device__ float g_erbf[EE * 24];     // per-edge: dir(3), rbf(20), pad
__device__ float g_WwT[20 * TF];      // Ww transposed [k][j]
__device__ int   g_cnt[NN];
__device__ int   g_off[NN + 1];
__device__ int   g_cur[NN];
__device__ int   g_eid[EE];

// ---------------- small elementwise kernels ----------------
__global__ void k_embed(const float* __restrict__ emb, const int* __restrict__ z) {
    int i = blockIdx.x * 256 + threadIdx.x;          // exactly NN*FF threads
    int n = i >> 7, f = i & 127;
    g_S[i] = emb[z[n] * FF + f];
}

__global__ void k_zero_cnt() {
    int i = blockIdx.x * 256 + threadIdx.x;
    if (i < NN) g_cnt[i] = 0;
}

__global__ void k_count(const int* __restrict__ dst) {
    int e = blockIdx.x * 256 + threadIdx.x;
    if (e < EE) atomicAdd(&g_cnt[dst[e]], 1);
}

__global__ void k_scan() {
    __shared__ int wsum[32];
    __shared__ int s_carry;
    int tid = threadIdx.x, lane = tid & 31, wid = tid >> 5;
    if (tid == 0) s_carry = 0;
    __syncthreads();
    for (int base = 0; base < NN; base += 1024) {
        int i = base + tid;
        int x = (i < NN) ? g_cnt[i] : 0;
        int v = x;
        #pragma unroll
        for (int d = 1; d < 32; d <<= 1) {
            int y = __shfl_up_sync(0xffffffffu, v, d);
            if (lane >= d) v += y;
        }
        if (lane == 31) wsum[wid] = v;
        __syncthreads();
        if (wid == 0) {
            int s = wsum[lane];
            #pragma unroll
            for (int d = 1; d < 32; d <<= 1) {
                int y = __shfl_up_sync(0xffffffffu, s, d);
                if (lane >= d) s += y;
            }
            wsum[lane] = s;
        }
        __syncthreads();
        int pre = (wid > 0) ? wsum[wid - 1] : 0;
        int carry = s_carry;
        if (i < NN) g_off[i] = carry + pre + v - x;   // exclusive
        __syncthreads();
        if (tid == 0) s_carry = carry + wsum[31];
        __syncthreads();
    }
    if (threadIdx.x == 0) g_off[NN] = EE;
}

__global__ void k_copy_cur() {
    int i = blockIdx.x * 256 + threadIdx.x;
    if (i < NN) g_cur[i] = g_off[i];
}

__global__ void k_scatter(const int* __restrict__ dst) {
    int e = blockIdx.x * 256 + threadIdx.x;
    if (e < EE) {
        int p = atomicAdd(&g_cur[dst[e]], 1);
        g_eid[p] = e;
    }
}

__global__ void k_wwt(const float* __restrict__ Ww) {
    int i = blockIdx.x * 256 + threadIdx.x;
    if (i < TF * 20) {
        int j = i / 20, k = i % 20;
        g_WwT[k * TF + j] = Ww[i];
    }
}

// per-edge scalars: direction + rbf
__global__ void k_edge(const float* __restrict__ pos, const int* __restrict__ src,
                       const int* __restrict__ dst) {
    int e = blockIdx.x * 256 + threadIdx.x;
    if (e >= EE) return;
    int s = src[e], d = dst[e];
    float rx = pos[d * 3 + 0] - pos[s * 3 + 0];
    float ry = pos[d * 3 + 1] - pos[s * 3 + 1];
    float rz = pos[d * 3 + 2] - pos[s * 3 + 2];
    float dist = sqrtf(rx * rx + ry * ry + rz * rz);
    dist = fmaxf(dist, 1e-9f);
    float inv = 1.0f / dist;
    float buf[24];
    buf[0] = rx * inv; buf[1] = ry * inv; buf[2] = rz * inv;
    float c = 3.14159265358979f * dist * 0.2f;   // pi*d/CUTOFF
    #pragma unroll
    for (int k = 0; k < 20; k++) buf[3 + k] = sinf((float)(k + 1) * c) * inv;
    buf[23] = 0.0f;
    float4* o = (float4*)(g_erbf + (size_t)e * 24);
    #pragma unroll
    for (int q = 0; q < 6; q++) o[q] = ((float4*)buf)[q];
}

// ---------------- gather-style message accumulation (no fp atomics) ----------------
__global__ void __launch_bounds__(128) k_gather(const int* __restrict__ src,
                                                const float* __restrict__ bw) {
    int t = threadIdx.x;       // feature index 0..127
    float w0[20], w2[20];
    #pragma unroll
    for (int k = 0; k < 20; k++) {
        w0[k] = g_WwT[k * TF + t];
        w2[k] = g_WwT[k * TF + 256 + t];
    }
    float b0 = bw[t], b2 = bw[256 + t];
    int nbase = blockIdx.x * 32;
    for (int ii = 0; ii < 32; ii++) {
        int n = nbase + ii;
        if (n >= NN) return;
        float accs = 0.f, av0 = 0.f, av1 = 0.f, av2 = 0.f;
        int e0 = g_off[n], e1 = g_off[n + 1];
        for (int idx = e0; idx < e1; idx++) {
            int e = g_eid[idx];
            const float4* eb = (const float4*)(g_erbf + (size_t)e * 24);
            float4 q0 = eb[0], q1 = eb[1], q2 = eb[2], q3 = eb[3], q4 = eb[4], q5 = eb[5];
            int s = src[e];
            float p0 = g_phi[(size_t)s * TF + t];
            float p2 = g_phi[(size_t)s * TF + 256 + t];
            float r[20];
            r[0] = q0.w;
            r[1] = q1.x; r[2] = q1.y; r[3] = q1.z; r[4] = q1.w;
            r[5] = q2.x; r[6] = q2.y; r[7] = q2.z; r[8] = q2.w;
            r[9] = q3.x; r[10] = q3.y; r[11] = q3.z; r[12] = q3.w;
            r[13] = q4.x; r[14] = q4.y; r[15] = q4.z; r[16] = q4.w;
            r[17] = q5.x; r[18] = q5.y; r[19] = q5.z;
            float wf0 = b0, wf2 = b2;
            #pragma unroll
            for (int k = 0; k < 20; k++) {
                wf0 = fmaf(r[k], w0[k], wf0);
                wf2 = fmaf(r[k], w2[k], wf2);
            }
            float m0 = p0 * wf0;
            float m2 = p2 * wf2;
            accs += m0;
            av0 = fmaf(m2, q0.x, av0);
            av1 = fmaf(m2, q0.y, av1);
            av2 = fmaf(m2, q0.z, av2);
        }
        g_h[n * 256 + t] = g_S[n * FF + t] + accs;     // s after message
        g_v[(n * 3 + 0) * FF + t] = av0;
        g_v[(n * 3 + 1) * FF + t] = av1;
        g_v[(n * 3 + 2) * FF + t] = av2;
    }
}

// ---------------- fused 2-layer MLP (silu hidden), 64 rows/block ----------------
// WHICH==0: phi = silu(S@Wp1^T+b)@Wp2^T+b  (KIN=128, in=g_S, out=g_phi)
// WHICH==1: a   = silu(h@Wu1^T+b)@Wu2^T+b  (KIN=256, in=g_h, out=g_a)
template <int WHICH>
__global__ void __launch_bounds__(256) k_mlp(const float* __restrict__ W1,
                                             const float* __restrict__ b1,
                                             const float* __restrict__ W2,
                                             const float* __restrict__ b2) {
    constexpr int KIN = (WHICH == 0) ? 128 : 256;
    const float* in = (WHICH == 0) ? g_S : g_h;
    float* out = (WHICH == 0) ? g_phi : g_a;

    __shared__ float As[16][64];
    __shared__ float Ws[16][128];
    __shared__ float Hs[64][132];

    int tid = threadIdx.x;
    int cg = tid & 15, rg = tid >> 4;
    int rowbase = blockIdx.x * 64;
    int lr = tid >> 2, lk4 = (tid & 3) * 4;   // A-tile loader coords
    int lo = tid >> 1, lk8 = (tid & 1) * 8;   // W-tile loader coords

    float acc[4][8];
    #pragma unroll
    for (int i = 0; i < 4; i++)
        #pragma unroll
        for (int j = 0; j < 8; j++) acc[i][j] = 0.f;

    // ---- layer 1 ----
    for (int kb = 0; kb < KIN; kb += 16) {
        {
            int row = rowbase + lr;
            float4 v = make_float4(0.f, 0.f, 0.f, 0.f);
            if (row < NN) v = *(const float4*)&in[(size_t)row * KIN + kb + lk4];
            As[lk4 + 0][lr] = v.x; As[lk4 + 1][lr] = v.y;
            As[lk4 + 2][lr] = v.z; As[lk4 + 3][lr] = v.w;
        }
        {
            const float* wr = W1 + (size_t)lo * KIN + kb + lk8;
            float4 a = *(const float4*)wr;
            float4 b = *(const float4*)(wr + 4);
            Ws[lk8 + 0][lo] = a.x; Ws[lk8 + 1][lo] = a.y;
            Ws[lk8 + 2][lo] = a.z; Ws[lk8 + 3][lo] = a.w;
            Ws[lk8 + 4][lo] = b.x; Ws[lk8 + 5][lo] = b.y;
            Ws[lk8 + 6][lo] = b.z; Ws[lk8 + 7][lo] = b.w;
        }
        __syncthreads();
        #pragma unroll
        for (int kk = 0; kk < 16; kk++) {
            float4 a4 = *(const float4*)&As[kk][rg * 4];
            float4 wA = *(const float4*)&Ws[kk][cg * 4];
            float4 wB = *(const float4*)&Ws[kk][64 + cg * 4];
            float av[4] = {a4.x, a4.y, a4.z, a4.w};
            float wv[8] = {wA.x, wA.y, wA.z, wA.w, wB.x, wB.y, wB.z, wB.w};
            #pragma unroll
            for (int i = 0; i < 4; i++)
                #pragma unroll
                for (int j = 0; j < 8; j++) acc[i][j] = fmaf(av[i], wv[j], acc[i][j]);
        }
        __syncthreads();
    }
    // silu + bias -> Hs  (layout [row][k], padded)
    {
        float4 u0 = *(const float4*)&b1[cg * 4];
        float4 u1 = *(const float4*)&b1[64 + cg * 4];
        float bb[8] = {u0.x, u0.y, u0.z, u0.w, u1.x, u1.y, u1.z, u1.w};
        #pragma unroll
        for (int i = 0; i < 4; i++) {
            float h[8];
            #pragma unroll
            for (int j = 0; j < 8; j++) {
                float x = acc[i][j] + bb[j];
                h[j] = x / (1.0f + expf(-x));
            }
            *(float4*)&Hs[rg * 4 + i][cg * 4] = make_float4(h[0], h[1], h[2], h[3]);
            *(float4*)&Hs[rg * 4 + i][64 + cg * 4] = make_float4(h[4], h[5], h[6], h[7]);
        }
    }
    __syncthreads();

    // ---- layer 2: 3 output blocks of 128 ----
    for (int ob = 0; ob < 3; ob++) {
        #pragma unroll
        for (int i = 0; i < 4; i++)
            #pragma unroll
            for (int j = 0; j < 8; j++) acc[i][j] = 0.f;
        for (int kb = 0; kb < 128; kb += 16) {
            {
                const float* wr = W2 + (size_t)(ob * 128 + lo) * 128 + kb + lk8;
                float4 a = *(const float4*)wr;
                float4 b = *(const float4*)(wr + 4);
                Ws[lk8 + 0][lo] = a.x; Ws[lk8 + 1][lo] = a.y;
                Ws[lk8 + 2][lo] = a.z; Ws[lk8 + 3][lo] = a.w;
                Ws[lk8 + 4][lo] = b.x; Ws[lk8 + 5][lo] = b.y;
                Ws[lk8 + 6][lo] = b.z; Ws[lk8 + 7][lo] = b.w;
            }
            __syncthreads();
            #pragma unroll
            for (int kk = 0; kk < 16; kk++) {
                float av[4];
                #pragma unroll
                for (int i = 0; i < 4; i++) av[i] = Hs[rg * 4 + i][kb + kk];
                float4 wA = *(const float4*)&Ws[kk][cg * 4];
                float4 wB = *(const float4*)&Ws[kk][64 + cg * 4];
                float wv[8] = {wA.x, wA.y, wA.z, wA.w, wB.x, wB.y, wB.z, wB.w};
                #pragma unroll
                for (int i = 0; i < 4; i++)
                    #pragma unroll
                    for (int j = 0; j < 8; j++) acc[i][j] = fmaf(av[i], wv[j], acc[i][j]);
            }
            __syncthreads();
        }
        float4 u0 = *(const float4*)&b2[ob * 128 + cg * 4];
        float4 u1 = *(const float4*)&b2[ob * 128 + 64 + cg * 4];
        #pragma unroll
        for (int i = 0; i < 4; i++) {
            int row = rowbase + rg * 4 + i;
            if (row < NN) {
                *(float4*)&out[(size_t)row * TF + ob * 128 + cg * 4] =
                    make_float4(acc[i][0] + u0.x, acc[i][1] + u0.y,
                                acc[i][2] + u0.z, acc[i][3] + u0.w);
                *(float4*)&out[(size_t)row * TF + ob * 128 + 64 + cg * 4] =
                    make_float4(acc[i][4] + u1.x, acc[i][5] + u1.y,
                                acc[i][6] + u1.z, acc[i][7] + u1.w);
            }
        }
    }
}

// ---------------- dual GEMM: U = v@Wu^T+bu, V = v@Wv^T+bv, M = 3N rows ----------------
__global__ void __launch_bounds__(256) k_uv(const float* __restrict__ Wu,
                                            const float* __restrict__ bu,
                                            const float* __restrict__ Wv,
                                            const float* __restrict__ bv) {
    const int M = NN * 3;
    __shared__ float As[16][64];
    __shared__ float WsU[16][128];
    __shared__ float WsV[16][128];

    int tid = threadIdx.x;
    int cg = tid & 15, rg = tid >> 4;
    int rowbase = blockIdx.x * 64;
    int lr = tid >> 2, lk4 = (tid & 3) * 4;
    int lo = tid >> 1, lk8 = (tid & 1) * 8;

    float accU[4][8], accV[4][8];
    #pragma unroll
    for (int i = 0; i < 4; i++)
        #pragma unroll
        for (int j = 0; j < 8; j++) { accU[i][j] = 0.f; accV[i][j] = 0.f; }

    for (int kb = 0; kb < 128; kb += 16) {
        {
            int row = rowbase + lr;
            float4 v = make_float4(0.f, 0.f, 0.f, 0.f);
            if (row < M) v = *(const float4*)&g_v[(size_t)row * 128 + kb + lk4];
            As[lk4 + 0][lr] = v.x; As[lk4 + 1][lr] = v.y;
            As[lk4 + 2][lr] = v.z; As[lk4 + 3][lr] = v.w;
        }
        {
            const float* wr = Wu + (size_t)lo * 128 + kb + lk8;
            float4 a = *(const float4*)wr;
            float4 b = *(const float4*)(wr + 4);
            WsU[lk8 + 0][lo] = a.x; WsU[lk8 + 1][lo] = a.y;
            WsU[lk8 + 2][lo] = a.z; WsU[lk8 + 3][lo] = a.w;
            WsU[lk8 + 4][lo] = b.x; WsU[lk8 + 5][lo] = b.y;
            WsU[lk8 + 6][lo] = b.z; WsU[lk8 + 7][lo] = b.w;
        }
        {
            const float* wr = Wv + (size_t)lo * 128 + kb + lk8;
            float4 a = *(const float4*)wr;
            float4 b = *(const float4*)(wr + 4);
            WsV[lk8 + 0][lo] = a.x; WsV[lk8 + 1][lo] = a.y;
            WsV[lk8 + 2][lo] = a.z; WsV[lk8 + 3][lo] = a.w;
            WsV[lk8 + 4][lo] = b.x; WsV[lk8 + 5][lo] = b.y;
            WsV[lk8 + 6][lo] = b.z; WsV[lk8 + 7][lo] = b.w;
        }
        __syncthreads();
        #pragma unroll
        for (int kk = 0; kk < 16; kk++) {
            float4 a4 = *(const float4*)&As[kk][rg * 4];
            float av[4] = {a4.x, a4.y, a4.z, a4.w};
            float4 uA = *(const float4*)&WsU[kk][cg * 4];
            float4 uB = *(const float4*)&WsU[kk][64 + cg * 4];
            float4 vA = *(const float4*)&WsV[kk][cg * 4];
            float4 vB = *(const float4*)&WsV[kk][64 + cg * 4];
            float wu[8] = {uA.x, uA.y, uA.z, uA.w, uB.x, uB.y, uB.z, uB.w};
            float wv[8] = {vA.x, vA.y, vA.z, vA.w, vB.x, vB.y, vB.z, vB.w};
            #pragma unroll
            for (int i = 0; i < 4; i++)
                #pragma unroll
                for (int j = 0; j < 8; j++) {
                    accU[i][j] = fmaf(av[i], wu[j], accU[i][j]);
                    accV[i][j] = fmaf(av[i], wv[j], accV[i][j]);
                }
        }
        __syncthreads();
    }
    float4 bu0 = *(const float4*)&bu[cg * 4];
    float4 bu1 = *(const float4*)&bu[64 + cg * 4];
    float4 bv0 = *(const float4*)&bv[cg * 4];
    float4 bv1 = *(const float4*)&bv[64 + cg * 4];
    #pragma unroll
    for (int i = 0; i < 4; i++) {
        int row = rowbase + rg * 4 + i;
        if (row < M) {
            *(float4*)&g_U[(size_t)row * 128 + cg * 4] =
                make_float4(accU[i][0] + bu0.x, accU[i][1] + bu0.y,
                            accU[i][2] + bu0.z, accU[i][3] + bu0.w);
            *(float4*)&g_U[(size_t)row * 128 + 64 + cg * 4] =
                make_float4(accU[i][4] + bu1.x, accU[i][5] + bu1.y,
                            accU[i][6] + bu1.z, accU[i][7] + bu1.w);
            *(float4*)&g_V[(size_t)row * 128 + cg * 4] =
                make_float4(accV[i][0] + bv0.x, accV[i][1] + bv0.y,
                            accV[i][2] + bv0.z, accV[i][3] + bv0.w);
            *(float4*)&g_V[(size_t)row * 128 + 64 + cg * 4] =
                make_float4(accV[i][4] + bv1.x, accV[i][5] + bv1.y,
                            accV[i][6] + bv1.z, accV[i][7] + bv1.w);
        }
    }
}

__global__ void k_vn() {
    int i = blockIdx.x * 256 + threadIdx.x;      // exactly NN*FF threads
    int n = i >> 7, f = i & 127;
    float x = g_V[(n * 3 + 0) * FF + f];
    float y = g_V[(n * 3 + 1) * FF + f];
    float z = g_V[(n * 3 + 2) * FF + f];
    g_h[n * 256 + 128 + f] = sqrtf(x * x + y * y + z * z);
}

__global__ void k_final(float* __restrict__ out) {
    int i = blockIdx.x * 256 + threadIdx.x;      // exactly NN*FF threads
    int n = i >> 7, f = i & 127;
    const float* ga = g_a + (size_t)n * TF;
    float a1 = ga[f], a2 = ga[128 + f], a3 = ga[256 + f];
    float dot = 0.f;
    float vo[3];
    #pragma unroll
    for (int c = 0; c < 3; c++) {
        int idx = (n * 3 + c) * FF + f;
        float Uc = g_U[idx], Vc = g_V[idx];
        dot = fmaf(Uc, Vc, dot);
        vo[c] = g_v[idx] + Uc * a1;
    }
    out[i] = g_h[n * 256 + f] + a2 + dot * a3;
    float* vp = out + (size_t)NN * FF + (size_t)i * 3;
    vp[0] = vo[0]; vp[1] = vo[1]; vp[2] = vo[2];
}

// ---------------- launch ----------------
extern "C" void kernel_launch(void* const* d_in, const int* in_sizes, int n_in,
                              void* d_out, int out_size) {
    const float* pos = (const float*)d_in[0];
    const float* emb = (const float*)d_in[1];
    const float* Wp1 = (const float*)d_in[2];
    const float* bp1 = (const float*)d_in[3];
    const float* Wp2 = (const float*)d_in[4];
    const float* bp2 = (const float*)d_in[5];
    const float* Ww  = (const float*)d_in[6];
    const float* bw  = (const float*)d_in[7];
    const float* Wu  = (const float*)d_in[8];
    const float* bu  = (const float*)d_in[9];
    const float* Wv  = (const float*)d_in[10];
    const float* bv  = (const float*)d_in[11];
    const float* Wu1 = (const float*)d_in[12];
    const float* bu1 = (const float*)d_in[13];
    const float* Wu2 = (const float*)d_in[14];
    const float* bu2 = (const float*)d_in[15];
    const int* z   = (const int*)d_in[16];
    const int* src = (const int*)d_in[17];
    const int* dst = (const int*)d_in[18];
    float* out = (float*)d_out;

    const int gridNF = (NN * FF) / 256;          // 25000
    const int gridE  = (EE + 255) / 256;         // 1563
    const int gridN  = (NN + 255) / 256;         // 196
    const int gridM64  = (NN + 63) / 64;         // 782
    const int gridM64x3 = (NN * 3 + 63) / 64;    // 2344
    const int gridGather = (NN + 31) / 32;       // 1563

    k_embed<<<gridNF, 256>>>(emb, z);
    k_mlp<0><<<gridM64, 256>>>(Wp1, bp1, Wp2, bp2);

    k_zero_cnt<<<gridN, 256>>>();
    k_count<<<gridE, 256>>>(dst);
    k_scan<<<1, 1024>>>();
    k_copy_cur<<<gridN, 256>>>();
    k_scatter<<<gridE, 256>>>(dst);

    k_edge<<<gridE, 256>>>(pos, src, dst);
    k_wwt<<<(TF * 20 + 255) / 256, 256>>>(Ww);

    k_gather<<<gridGather, 128>>>(src, bw);

    k_uv<<<gridM64x3, 256>>>(Wu, bu, Wv, bv);
    k_vn<<<gridNF, 256>>>();
    k_mlp<1><<<gridM64, 256>>>(Wu1, bu1, Wu2, bu2);
    k_final<<<gridNF, 256>>>(out);
}

// round 5
// speedup vs baseline: 1.0121x; 1.0121x over previous
#include <cuda_runtime.h>
#include <math.h>

#define NN 50000
#define EE 400000
#define FF 128
#define TF 384

// ---------------- packed f32x2 helpers (FFMA2: 2x fp32 throughput) ----------------
__device__ __forceinline__ unsigned long long pk2(float x, float y) {
    unsigned long long r;
    asm("mov.b64 %0,{%1,%2};" : "=l"(r) : "f"(x), "f"(y));
    return r;
}
__device__ __forceinline__ void upk2(unsigned long long p, float& x, float& y) {
    asm("mov.b64 {%0,%1},%2;" : "=f"(x), "=f"(y) : "l"(p));
}
__device__ __forceinline__ unsigned long long ffma2(unsigned long long a,
                                                    unsigned long long b,
                                                    unsigned long long c) {
    unsigned long long d;
    asm("fma.rn.f32x2 %0,%1,%2,%3;" : "=l"(d) : "l"(a), "l"(b), "l"(c));
    return d;
}

// ---------------- device scratch (static, no allocation) ----------------
__device__ float g_S[NN * FF];        // embedded scalar features s0
__device__ float g_phi[NN * TF];      // phi = MLP(s0)
__device__ float g_h[NN * 256];       // [ :128]=s_msg, [128:256]=Vn
__device__ float g_v[NN * TF];        // message-phase v, layout [n][c][f]
__device__ float g_U[NN * TF];        // U, layout [n][c][f]
__device__ float g_V[NN * TF];        // V, layout [n][c][f]
__device__ float g_a[NN * TF];        // update-MLP output a
__device__ float g_erbf[EE * 24];     // per-edge: dir(3), rbf(20), pad
__device__ float g_WwT[20 * TF];      // Ww transposed [k][j]
__device__ int   g_cnt[NN];
__device__ int   g_off[NN + 1];
__device__ int   g_cur[NN];
__device__ int   g_eid[EE];

// ---------------- small elementwise kernels ----------------
__global__ void k_embed(const float* __restrict__ emb, const int* __restrict__ z) {
    int i = blockIdx.x * 256 + threadIdx.x;          // exactly NN*FF threads
    int n = i >> 7, f = i & 127;
    g_S[i] = emb[z[n] * FF + f];
}

__global__ void k_zero_cnt() {
    int i = blockIdx.x * 256 + threadIdx.x;
    if (i < NN) g_cnt[i] = 0;
}

__global__ void k_count(const int* __restrict__ dst) {
    int e = blockIdx.x * 256 + threadIdx.x;
    if (e < EE) atomicAdd(&g_cnt[dst[e]], 1);
}

__global__ void k_scan() {
    __shared__ int wsum[32];
    __shared__ int s_carry;
    int tid = threadIdx.x, lane = tid & 31, wid = tid >> 5;
    if (tid == 0) s_carry = 0;
    __syncthreads();
    for (int base = 0; base < NN; base += 1024) {
        int i = base + tid;
        int x = (i < NN) ? g_cnt[i] : 0;
        int v = x;
        #pragma unroll
        for (int d = 1; d < 32; d <<= 1) {
            int y = __shfl_up_sync(0xffffffffu, v, d);
            if (lane >= d) v += y;
        }
        if (lane == 31) wsum[wid] = v;
        __syncthreads();
        if (wid == 0) {
            int s = wsum[lane];
            #pragma unroll
            for (int d = 1; d < 32; d <<= 1) {
                int y = __shfl_up_sync(0xffffffffu, s, d);
                if (lane >= d) s += y;
            }
            wsum[lane] = s;
        }
        __syncthreads();
        int pre = (wid > 0) ? wsum[wid - 1] : 0;
        int carry = s_carry;
        if (i < NN) g_off[i] = carry + pre + v - x;   // exclusive
        __syncthreads();
        if (tid == 0) s_carry = carry + wsum[31];
        __syncthreads();
    }
    if (threadIdx.x == 0) g_off[NN] = EE;
}

__global__ void k_copy_cur() {
    int i = blockIdx.x * 256 + threadIdx.x;
    if (i < NN) g_cur[i] = g_off[i];
}

__global__ void k_scatter(const int* __restrict__ dst) {
    int e = blockIdx.x * 256 + threadIdx.x;
    if (e < EE) {
        int p = atomicAdd(&g_cur[dst[e]], 1);
        g_eid[p] = e;
    }
}

__global__ void k_wwt(const float* __restrict__ Ww) {
    int i = blockIdx.x * 256 + threadIdx.x;
    if (i < TF * 20) {
        int j = i / 20, k = i % 20;
        g_WwT[k * TF + j] = Ww[i];
    }
}

// per-edge scalars: direction + rbf (sincos recurrence instead of 20x sinf)
__global__ void k_edge(const float* __restrict__ pos, const int* __restrict__ src,
                       const int* __restrict__ dst) {
    int e = blockIdx.x * 256 + threadIdx.x;
    if (e >= EE) return;
    int s = src[e], d = dst[e];
    float rx = pos[d * 3 + 0] - pos[s * 3 + 0];
    float ry = pos[d * 3 + 1] - pos[s * 3 + 1];
    float rz = pos[d * 3 + 2] - pos[s * 3 + 2];
    float dist = sqrtf(rx * rx + ry * ry + rz * rz);
    dist = fmaxf(dist, 1e-9f);
    float inv = 1.0f / dist;
    float buf[24];
    buf[0] = rx * inv; buf[1] = ry * inv; buf[2] = rz * inv;
    float c = 3.14159265358979f * dist * 0.2f;   // pi*d/CUTOFF
    float sc, cc;
    sincosf(c, &sc, &cc);
    // sin(n*c) via angle addition: s_{n+1} = s_n*cc + c_n*sc ; c_{n+1} = c_n*cc - s_n*sc
    float sn = sc, cn = cc;
    buf[3] = sn * inv;
    #pragma unroll
    for (int k = 1; k < 20; k++) {
        float sn2 = fmaf(sn, cc, cn * sc);
        float cn2 = fmaf(cn, cc, -sn * sc);
        sn = sn2; cn = cn2;
        buf[3 + k] = sn * inv;
    }
    buf[23] = 0.0f;
    float4* o = (float4*)(g_erbf + (size_t)e * 24);
    #pragma unroll
    for (int q = 0; q < 6; q++) o[q] = ((float4*)buf)[q];
}

// ---------------- gather-style message accumulation (no fp atomics) ----------------
__global__ void __launch_bounds__(128) k_gather(const int* __restrict__ src,
                                                const float* __restrict__ bw) {
    int t = threadIdx.x;       // feature index 0..127
    float w0[20], w2[20];
    #pragma unroll
    for (int k = 0; k < 20; k++) {
        w0[k] = g_WwT[k * TF + t];
        w2[k] = g_WwT[k * TF + 256 + t];
    }
    float b0 = bw[t], b2 = bw[256 + t];
    int nbase = blockIdx.x * 32;
    for (int ii = 0; ii < 32; ii++) {
        int n = nbase + ii;
        if (n >= NN) return;
        float accs = 0.f, av0 = 0.f, av1 = 0.f, av2 = 0.f;
        int e0 = g_off[n], e1 = g_off[n + 1];
        for (int idx = e0; idx < e1; idx++) {
            int e = g_eid[idx];
            const float4* eb = (const float4*)(g_erbf + (size_t)e * 24);
            float4 q0 = eb[0], q1 = eb[1], q2 = eb[2], q3 = eb[3], q4 = eb[4], q5 = eb[5];
            int s = src[e];
            float p0 = g_phi[(size_t)s * TF + t];
            float p2 = g_phi[(size_t)s * TF + 256 + t];
            float r[20];
            r[0] = q0.w;
            r[1] = q1.x; r[2] = q1.y; r[3] = q1.z; r[4] = q1.w;
            r[5] = q2.x; r[6] = q2.y; r[7] = q2.z; r[8] = q2.w;
            r[9] = q3.x; r[10] = q3.y; r[11] = q3.z; r[12] = q3.w;
            r[13] = q4.x; r[14] = q4.y; r[15] = q4.z; r[16] = q4.w;
            r[17] = q5.x; r[18] = q5.y; r[19] = q5.z;
            float wf0 = b0, wf2 = b2;
            #pragma unroll
            for (int k = 0; k < 20; k++) {
                wf0 = fmaf(r[k], w0[k], wf0);
                wf2 = fmaf(r[k], w2[k], wf2);
            }
            float m0 = p0 * wf0;
            float m2 = p2 * wf2;
            accs += m0;
            av0 = fmaf(m2, q0.x, av0);
            av1 = fmaf(m2, q0.y, av1);
            av2 = fmaf(m2, q0.z, av2);
        }
        g_h[n * 256 + t] = g_S[n * FF + t] + accs;     // s after message
        g_v[(n * 3 + 0) * FF + t] = av0;
        g_v[(n * 3 + 1) * FF + t] = av1;
        g_v[(n * 3 + 2) * FF + t] = av2;
    }
}

// ---------------- fused 2-layer MLP (silu hidden), 64 rows/block, FFMA2 ----------------
// WHICH==0: phi = silu(S@Wp1^T+b)@Wp2^T+b  (KIN=128, in=g_S, out=g_phi)
// WHICH==1: a   = silu(h@Wu1^T+b)@Wu2^T+b  (KIN=256, in=g_h, out=g_a)
template <int WHICH>
__global__ void __launch_bounds__(256) k_mlp(const float* __restrict__ W1,
                                             const float* __restrict__ b1,
                                             const float* __restrict__ W2,
                                             const float* __restrict__ b2) {
    constexpr int KIN = (WHICH == 0) ? 128 : 256;
    const float* in = (WHICH == 0) ? g_S : g_h;
    float* out = (WHICH == 0) ? g_phi : g_a;

    __shared__ float As[16][64];
    __shared__ float Ws[16][128];
    __shared__ float Hs[64][132];

    int tid = threadIdx.x;
    int cg = tid & 15, rg = tid >> 4;
    int rowbase = blockIdx.x * 64;
    int lr = tid >> 2, lk4 = (tid & 3) * 4;   // A-tile loader coords
    int lo = tid >> 1, lk8 = (tid & 1) * 8;   // W-tile loader coords

    unsigned long long acc2[4][4];            // packed pairs of output cols
    #pragma unroll
    for (int i = 0; i < 4; i++)
        #pragma unroll
        for (int jp = 0; jp < 4; jp++) acc2[i][jp] = 0ull;

    // ---- layer 1 ----
    for (int kb = 0; kb < KIN; kb += 16) {
        {
            int row = rowbase + lr;
            float4 v = make_float4(0.f, 0.f, 0.f, 0.f);
            if (row < NN) v = *(const float4*)&in[(size_t)row * KIN + kb + lk4];
            As[lk4 + 0][lr] = v.x; As[lk4 + 1][lr] = v.y;
            As[lk4 + 2][lr] = v.z; As[lk4 + 3][lr] = v.w;
        }
        {
            const float* wr = W1 + (size_t)lo * KIN + kb + lk8;
            float4 a = *(const float4*)wr;
            float4 b = *(const float4*)(wr + 4);
            Ws[lk8 + 0][lo] = a.x; Ws[lk8 + 1][lo] = a.y;
            Ws[lk8 + 2][lo] = a.z; Ws[lk8 + 3][lo] = a.w;
            Ws[lk8 + 4][lo] = b.x; Ws[lk8 + 5][lo] = b.y;
            Ws[lk8 + 6][lo] = b.z; Ws[lk8 + 7][lo] = b.w;
        }
        __syncthreads();
        #pragma unroll
        for (int kk = 0; kk < 16; kk++) {
            float4 a4 = *(const float4*)&As[kk][rg * 4];
            ulonglong2 wA = *(const ulonglong2*)&Ws[kk][cg * 4];
            ulonglong2 wB = *(const ulonglong2*)&Ws[kk][64 + cg * 4];
            unsigned long long w2[4] = {wA.x, wA.y, wB.x, wB.y};
            float av[4] = {a4.x, a4.y, a4.z, a4.w};
            #pragma unroll
            for (int i = 0; i < 4; i++) {
                unsigned long long a2 = pk2(av[i], av[i]);
                #pragma unroll
                for (int jp = 0; jp < 4; jp++)
                    acc2[i][jp] = ffma2(a2, w2[jp], acc2[i][jp]);
            }
        }
        __syncthreads();
    }
    // silu + bias -> Hs  (layout [row][k], padded)
    {
        float4 u0 = *(const float4*)&b1[cg * 4];
        float4 u1 = *(const float4*)&b1[64 + cg * 4];
        float bb[8] = {u0.x, u0.y, u0.z, u0.w, u1.x, u1.y, u1.z, u1.w};
        #pragma unroll
        for (int i = 0; i < 4; i++) {
            float h[8];
            #pragma unroll
            for (int jp = 0; jp < 4; jp++) {
                float x0, x1;
                upk2(acc2[i][jp], x0, x1);
                x0 += bb[2 * jp]; x1 += bb[2 * jp + 1];
                h[2 * jp] = x0 / (1.0f + expf(-x0));
                h[2 * jp + 1] = x1 / (1.0f + expf(-x1));
            }
            *(float4*)&Hs[rg * 4 + i][cg * 4] = make_float4(h[0], h[1], h[2], h[3]);
            *(float4*)&Hs[rg * 4 + i][64 + cg * 4] = make_float4(h[4], h[5], h[6], h[7]);
        }
    }
    __syncthreads();

    // ---- layer 2: 3 output blocks of 128 ----
    for (int ob = 0; ob < 3; ob++) {
        #pragma unroll
        for (int i = 0; i < 4; i++)
            #pragma unroll
            for (int jp = 0; jp < 4; jp++) acc2[i][jp] = 0ull;
        for (int kb = 0; kb < 128; kb += 16) {
            {
                const float* wr = W2 + (size_t)(ob * 128 + lo) * 128 + kb + lk8;
                float4 a = *(const float4*)wr;
                float4 b = *(const float4*)(wr + 4);
                Ws[lk8 + 0][lo] = a.x; Ws[lk8 + 1][lo] = a.y;
                Ws[lk8 + 2][lo] = a.z; Ws[lk8 + 3][lo] = a.w;
                Ws[lk8 + 4][lo] = b.x; Ws[lk8 + 5][lo] = b.y;
                Ws[lk8 + 6][lo] = b.z; Ws[lk8 + 7][lo] = b.w;
            }
            __syncthreads();
            #pragma unroll
            for (int kk = 0; kk < 16; kk++) {
                ulonglong2 wA = *(const ulonglong2*)&Ws[kk][cg * 4];
                ulonglong2 wB = *(const ulonglong2*)&Ws[kk][64 + cg * 4];
                unsigned long long w2[4] = {wA.x, wA.y, wB.x, wB.y};
                #pragma unroll
                for (int i = 0; i < 4; i++) {
                    float av = Hs[rg * 4 + i][kb + kk];
                    unsigned long long a2 = pk2(av, av);
                    #pragma unroll
                    for (int jp = 0; jp < 4; jp++)
                        acc2[i][jp] = ffma2(a2, w2[jp], acc2[i][jp]);
                }
            }
            __syncthreads();
        }
        float4 u0 = *(const float4*)&b2[ob * 128 + cg * 4];
        float4 u1 = *(const float4*)&b2[ob * 128 + 64 + cg * 4];
        float bb[8] = {u0.x, u0.y, u0.z, u0.w, u1.x, u1.y, u1.z, u1.w};
        #pragma unroll
        for (int i = 0; i < 4; i++) {
            int row = rowbase + rg * 4 + i;
            if (row < NN) {
                float o[8];
                #pragma unroll
                for (int jp = 0; jp < 4; jp++) {
                    float x0, x1;
                    upk2(acc2[i][jp], x0, x1);
                    o[2 * jp] = x0 + bb[2 * jp];
                    o[2 * jp + 1] = x1 + bb[2 * jp + 1];
                }
                *(float4*)&out[(size_t)row * TF + ob * 128 + cg * 4] =
                    make_float4(o[0], o[1], o[2], o[3]);
                *(float4*)&out[(size_t)row * TF + ob * 128 + 64 + cg * 4] =
                    make_float4(o[4], o[5], o[6], o[7]);
            }
        }
    }
}

// ---------------- dual GEMM: U = v@Wu^T+bu, V = v@Wv^T+bv, M = 3N rows, FFMA2 ----------------
__global__ void __launch_bounds__(256) k_uv(const float* __restrict__ Wu,
                                            const float* __restrict__ bu,
                                            const float* __restrict__ Wv,
                                            const float* __restrict__ bv) {
    const int M = NN * 3;
    __shared__ float As[16][64];
    __shared__ float WsU[16][128];
    __shared__ float WsV[16][128];

    int tid = threadIdx.x;
    int cg = tid & 15, rg = tid >> 4;
    int rowbase = blockIdx.x * 64;
    int lr = tid >> 2, lk4 = (tid & 3) * 4;
    int lo = tid >> 1, lk8 = (tid & 1) * 8;

    unsigned long long accU2[4][4], accV2[4][4];
    #pragma unroll
    for (int i = 0; i < 4; i++)
        #pragma unroll
        for (int jp = 0; jp < 4; jp++) { accU2[i][jp] = 0ull; accV2[i][jp] = 0ull; }

    for (int kb = 0; kb < 128; kb += 16) {
        {
            int row = rowbase + lr;
            float4 v = make_float4(0.f, 0.f, 0.f, 0.f);
            if (row < M) v = *(const float4*)&g_v[(size_t)row * 128 + kb + lk4];
            As[lk4 + 0][lr] = v.x; As[lk4 + 1][lr] = v.y;
            As[lk4 + 2][lr] = v.z; As[lk4 + 3][lr] = v.w;
        }
        {
            const float* wr = Wu + (size_t)lo * 128 + kb + lk8;
            float4 a = *(const float4*)wr;
            float4 b = *(const float4*)(wr + 4);
            WsU[lk8 + 0][lo] = a.x; WsU[lk8 + 1][lo] = a.y;
            WsU[lk8 + 2][lo] = a.z; WsU[lk8 + 3][lo] = a.w;
            WsU[lk8 + 4][lo] = b.x; WsU[lk8 + 5][lo] = b.y;
            WsU[lk8 + 6][lo] = b.z; WsU[lk8 + 7][lo] = b.w;
        }
        {
            const float* wr = Wv + (size_t)lo * 128 + kb + lk8;
            float4 a = *(const float4*)wr;
            float4 b = *(const float4*)(wr + 4);
            WsV[lk8 + 0][lo] = a.x; WsV[lk8 + 1][lo] = a.y;
            WsV[lk8 + 2][lo] = a.z; WsV[lk8 + 3][lo] = a.w;
            WsV[lk8 + 4][lo] = b.x; WsV[lk8 + 5][lo] = b.y;
            WsV[lk8 + 6][lo] = b.z; WsV[lk8 + 7][lo] = b.w;
        }
        __syncthreads();
        #pragma unroll
        for (int kk = 0; kk < 16; kk++) {
            float4 a4 = *(const float4*)&As[kk][rg * 4];
            float av[4] = {a4.x, a4.y, a4.z, a4.w};
            ulonglong2 uA = *(const ulonglong2*)&WsU[kk][cg * 4];
            ulonglong2 uB = *(const ulonglong2*)&WsU[kk][64 + cg * 4];
            ulonglong2 vA = *(const ulonglong2*)&WsV[kk][cg * 4];
            ulonglong2 vB = *(const ulonglong2*)&WsV[kk][64 + cg * 4];
            unsigned long long wu[4] = {uA.x, uA.y, uB.x, uB.y};
            unsigned long long wv[4] = {vA.x, vA.y, vB.x, vB.y};
            #pragma unroll
            for (int i = 0; i < 4; i++) {
                unsigned long long a2 = pk2(av[i], av[i]);
                #pragma unroll
                for (int jp = 0; jp < 4; jp++) {
                    accU2[i][jp] = ffma2(a2, wu[jp], accU2[i][jp]);
                    accV2[i][jp] = ffma2(a2, wv[jp], accV2[i][jp]);
                }
            }
        }
        __syncthreads();
    }
    float4 bu0 = *(const float4*)&bu[cg * 4];
    float4 bu1 = *(const float4*)&bu[64 + cg * 4];
    float4 bv0 = *(const float4*)&bv[cg * 4];
    float4 bv1 = *(const float4*)&bv[64 + cg * 4];
    float bbu[8] = {bu0.x, bu0.y, bu0.z, bu0.w, bu1.x, bu1.y, bu1.z, bu1.w};
    float bbv[8] = {bv0.x, bv0.y, bv0.z, bv0.w, bv1.x, bv1.y, bv1.z, bv1.w};
    #pragma unroll
    for (int i = 0; i < 4; i++) {
        int row = rowbase + rg * 4 + i;
        if (row < M) {
            float ou[8], ov[8];
            #pragma unroll
            for (int jp = 0; jp < 4; jp++) {
                float x0, x1;
                upk2(accU2[i][jp], x0, x1);
                ou[2 * jp] = x0 + bbu[2 * jp];
                ou[2 * jp + 1] = x1 + bbu[2 * jp + 1];
                upk2(accV2[i][jp], x0, x1);
                ov[2 * jp] = x0 + bbv[2 * jp];
                ov[2 * jp + 1] = x1 + bbv[2 * jp + 1];
            }
            *(float4*)&g_U[(size_t)row * 128 + cg * 4] =
                make_float4(ou[0], ou[1], ou[2], ou[3]);
            *(float4*)&g_U[(size_t)row * 128 + 64 + cg * 4] =
                make_float4(ou[4], ou[5], ou[6], ou[7]);
            *(float4*)&g_V[(size_t)row * 128 + cg * 4] =
                make_float4(ov[0], ov[1], ov[2], ov[3]);
            *(float4*)&g_V[(size_t)row * 128 + 64 + cg * 4] =
                make_float4(ov[4], ov[5], ov[6], ov[7]);
        }
    }
}

__global__ void k_vn() {
    int i = blockIdx.x * 256 + threadIdx.x;      // exactly NN*FF threads
    int n = i >> 7, f = i & 127;
    float x = g_V[(n * 3 + 0) * FF + f];
    float y = g_V[(n * 3 + 1) * FF + f];
    float z = g_V[(n * 3 + 2) * FF + f];
    g_h[n * 256 + 128 + f] = sqrtf(x * x + y * y + z * z);
}

__global__ void k_final(float* __restrict__ out) {
    int i = blockIdx.x * 256 + threadIdx.x;      // exactly NN*FF threads
    int n = i >> 7, f = i & 127;
    const float* ga = g_a + (size_t)n * TF;
    float a1 = ga[f], a2 = ga[128 + f], a3 = ga[256 + f];
    float dot = 0.f;
    float vo[3];
    #pragma unroll
    for (int c = 0; c < 3; c++) {
        int idx = (n * 3 + c) * FF + f;
        float Uc = g_U[idx], Vc = g_V[idx];
        dot = fmaf(Uc, Vc, dot);
        vo[c] = g_v[idx] + Uc * a1;
    }
    out[i] = g_h[n * 256 + f] + a2 + dot * a3;
    float* vp = out + (size_t)NN * FF + (size_t)i * 3;
    vp[0] = vo[0]; vp[1] = vo[1]; vp[2] = vo[2];
}

// ---------------- launch ----------------
extern "C" void kernel_launch(void* const* d_in, const int* in_sizes, int n_in,
                              void* d_out, int out_size) {
    const float* pos = (const float*)d_in[0];
    const float* emb = (const float*)d_in[1];
    const float* Wp1 = (const float*)d_in[2];
    const float* bp1 = (const float*)d_in[3];
    const float* Wp2 = (const float*)d_in[4];
    const float* bp2 = (const float*)d_in[5];
    const float* Ww  = (const float*)d_in[6];
    const float* bw  = (const float*)d_in[7];
    const float* Wu  = (const float*)d_in[8];
    const float* bu  = (const float*)d_in[9];
    const float* Wv  = (const float*)d_in[10];
    const float* bv  = (const float*)d_in[11];
    const float* Wu1 = (const float*)d_in[12];
    const float* bu1 = (const float*)d_in[13];
    const float* Wu2 = (const float*)d_in[14];
    const float* bu2 = (const float*)d_in[15];
    const int* z   = (const int*)d_in[16];
    const int* src = (const int*)d_in[17];
    const int* dst = (const int*)d_in[18];
    float* out = (float*)d_out;

    const int gridNF = (NN * FF) / 256;          // 25000
    const int gridE  = (EE + 255) / 256;         // 1563
    const int gridN  = (NN + 255) / 256;         // 196
    const int gridM64  = (NN + 63) / 64;         // 782
    const int gridM64x3 = (NN * 3 + 63) / 64;    // 2344
    const int gridGather = (NN + 31) / 32;       // 1563

    k_embed<<<gridNF, 256>>>(emb, z);
    k_mlp<0><<<gridM64, 256>>>(Wp1, bp1, Wp2, bp2);

    k_zero_cnt<<<gridN, 256>>>();
    k_count<<<gridE, 256>>>(dst);
    k_scan<<<1, 1024>>>();
    k_copy_cur<<<gridN, 256>>>();
    k_scatter<<<gridE, 256>>>(dst);

    k_edge<<<gridE, 256>>>(pos, src, dst);
    k_wwt<<<(TF * 20 + 255) / 256, 256>>>(Ww);

    k_gather<<<gridGather, 128>>>(src, bw);

    k_uv<<<gridM64x3, 256>>>(Wu, bu, Wv, bv);
    k_vn<<<gridNF, 256>>>();
    k_mlp<1><<<gridM64, 256>>>(Wu1, bu1, Wu2, bu2);
    k_final<<<gridNF, 256>>>(out);
}